// round 15
// baseline (speedup 1.0000x reference)
#include <cuda_runtime.h>
#include <cuda_bf16.h>
#include <cstdint>
#include <math.h>

#define BB 48
#define SS 128
#define WW 4
#define KK 256
#define NT 512
#define ROWB 528           // v-ring slot stride (bytes): 132 words -> conflict-free

#define MMA_BF16(d0, d1, d2, d3, a, b0, b1)                                   \
    asm volatile(                                                             \
        "mma.sync.aligned.m16n8k16.row.col.f32.bf16.bf16.f32 "                \
        "{%0,%1,%2,%3}, {%4,%5,%6,%7}, {%8,%9}, {%0,%1,%2,%3};"               \
        : "+f"(d0), "+f"(d1), "+f"(d2), "+f"(d3)                              \
        : "r"((a)[0]), "r"((a)[1]), "r"((a)[2]), "r"((a)[3]),                 \
          "r"(b0), "r"(b1))

static __device__ __forceinline__ uint32_t redux_max_u32(uint32_t v) {
    uint32_t r;
    asm("redux.sync.max.u32 %0, %1, 0xffffffff;" : "=r"(r) : "r"(v));
    return r;
}
static __device__ __forceinline__ uint32_t fkey(float f) {
    uint32_t u = __float_as_uint(f);
    return (u & 0x80000000u) ? ~u : (u | 0x80000000u);
}
static __device__ __forceinline__ float funkey(uint32_t k) {
    return __uint_as_float((k & 0x80000000u) ? (k & 0x7fffffffu) : ~k);
}

extern "C" __global__ void __launch_bounds__(NT, 1)
crf_hmma8_kernel(const float* __restrict__ logits,
                 const float* __restrict__ T,
                 const float* __restrict__ hc,
                 const float* __restrict__ tagm,
                 const int*   __restrict__ textmask,
                 float* __restrict__ out)
{
    __shared__ float  sAlpha[KK];         // latest alpha row (for final lse only)
    __shared__ float  sE[2][KK][4];       // emissions, double-buffered
    __shared__ float  sRedL[4][16];       // warp maxes, 4-slot ring
    __shared__ float  sTm[KK];
    __shared__ float  sRed[32];
    __shared__ __align__(4) unsigned char vsm[8 * ROWB];   // bf16 v-ring, 8 slots

    const int tid  = threadIdx.x;
    const int lane = tid & 31;
    const int wid  = tid >> 5;            // M-tile 0..15
    const int b    = blockIdx.x;

    // ---- length[b] ----
    {
        int tt = (tid < SS) ? textmask[b * SS + tid] : 0;
        #pragma unroll
        for (int o = 16; o; o >>= 1) tt += __shfl_xor_sync(0xffffffffu, tt, o);
        if (lane == 0) sRed[wid] = (float)tt;
    }
    __syncthreads();
    int L = 0;
    #pragma unroll
    for (int i = 0; i < 16; i++) L += (int)sRed[i];
    __syncthreads();
    if (L == 0) { if (tid == 0) out[b] = logf(256.0f); return; }
    const int JMAX = (L < SS) ? L : SS;

    // ---- zero v-ring ----
    {
        uint32_t* vz = (uint32_t*)vsm;
        for (int i = tid; i < (8 * ROWB) / 4; i += NT) vz[i] = 0u;
    }

    // ---- prologue: A frags, full K (16 chunks), rows rg0 / rg0+8 ----
    const size_t tb  = (size_t)b * KK * KK;
    const int    rg0 = (wid << 4) + (lane >> 2);
    const int    kq  = (lane & 3) << 1;
    uint32_t A[16][4];
    {
        const float* Tr0 = T    + tb + (size_t)rg0 * KK;
        const float* Mr0 = tagm + tb + (size_t)rg0 * KK;
        const float* Tr1 = Tr0 + 8 * KK;
        const float* Mr1 = Mr0 + 8 * KK;
        #pragma unroll
        for (int c = 0; c < 16; c++) {
            #pragma unroll
            for (int h2 = 0; h2 < 2; h2++) {
                const int kk2 = c * 16 + kq + h2 * 8;
                float2 t0 = *(const float2*)(Tr0 + kk2);
                float2 m0 = *(const float2*)(Mr0 + kk2);
                float2 t1 = *(const float2*)(Tr1 + kk2);
                float2 m1 = *(const float2*)(Mr1 + kk2);
                __nv_bfloat162 p0 =
                    __floats2bfloat162_rn(__expf(t0.x * m0.x), __expf(t0.y * m0.y));
                __nv_bfloat162 p1 =
                    __floats2bfloat162_rn(__expf(t1.x * m1.x), __expf(t1.y * m1.y));
                A[c][h2 * 2 + 0] = *(uint32_t*)&p0;
                A[c][h2 * 2 + 1] = *(uint32_t*)&p1;
            }
        }
    }

    // ---- sTm + sE[0] ----
    if (tid < KK) sTm[tid] = tagm[tb + tid];
    __syncthreads();
    {
        const int k_l = tid >> 1, wp = (tid & 1) * 2;
        const size_t ei = (((size_t)b * SS + 0) * WW + wp) * KK + k_l;
        const float tm = sTm[k_l];
        sE[0][k_l][wp]     = (__ldg(logits + ei     ) + __ldg(hc + ei     )) * tm;
        sE[0][k_l][wp + 1] = (__ldg(logits + ei + KK) + __ldg(hc + ei + KK)) * tm;
    }

    // σ history: s0 = σ_j (scale of row written this step) = rowmax_{j-2};
    // epilogue w=n uses σ_{j-1-n} = s_{n+1}.
    float s0 = 0.f, s1 = 0.f, s2 = 0.f, s3 = 0.f, s4 = 0.f;

    for (int j = 0; j < JMAX; j++) {
        const int nT   = (j < WW) ? j : WW;
        const int slot = j & 7;

        __syncthreads();   // bar0: epilogue(j-1) v-ring/sRedL/sE writes visible

        // ---- σ shift: s0 = rowmax_{j-2} ----
        float ns = 0.f;
        if (j >= 2) {
            float x = (lane < 16) ? sRedL[(j - 2) & 3][lane] : -1e30f;
            ns = funkey(redux_max_u32(fkey(x)));
        }
        s4 = s3; s3 = s2; s2 = s1; s1 = s0; s0 = ns;
        float M = (j < WW) ? 0.0f : -1e30f;
        if (nT > 0) M = fmaxf(M, s1);
        if (nT > 1) M = fmaxf(M, s2);
        if (nT > 2) M = fmaxf(M, s3);
        if (nT > 3) M = fmaxf(M, s4);

        // ---- emission LDGs for j+1 (all threads; land during MMA+epilogue) ----
        float l0 = 0.f, l1 = 0.f, q0 = 0.f, q1 = 0.f;
        const int k_l = tid >> 1, wp = (tid & 1) * 2;
        if ((j + 1) < JMAX) {
            const size_t ei = (((size_t)b * SS + (j + 1)) * WW + wp) * KK + k_l;
            l0 = __ldg(logits + ei);      q0 = __ldg(hc + ei);
            l1 = __ldg(logits + ei + KK); q1 = __ldg(hc + ei + KK);
        }

        // ---- MMA: full K, 16 chunks (2 interleaved chains of 8) ----
        float d0 = 0.f, d1 = 0.f, d2 = 0.f, d3 = 0.f;
        {
            float f0 = 0.f, f1 = 0.f, f2 = 0.f, f3 = 0.f;
            const int      n8    = lane >> 2;
            const uint32_t bboff = (uint32_t)(lane & 3) << 2;
            const uint32_t rowoff =
                (uint32_t)((j - 1 - n8) & 7) * ROWB + bboff;
            #pragma unroll
            for (int c = 0; c < 16; c += 2) {
                uint32_t b0 = 0, b1 = 0, b2 = 0, b3 = 0;
                if (n8 < 4) {
                    const unsigned char* vp = vsm + rowoff + (c << 5);
                    b0 = *(const uint32_t*)(vp);
                    b1 = *(const uint32_t*)(vp + 16);
                    b2 = *(const uint32_t*)(vp + 32);
                    b3 = *(const uint32_t*)(vp + 48);
                }
                MMA_BF16(d0, d1, d2, d3, A[c],     b0, b1);
                MMA_BF16(f0, f1, f2, f3, A[c + 1], b2, b3);
            }
            d0 += f0; d1 += f1; d2 += f2; d3 += f3;
        }

        // ---- split epilogue (w=n uses scale s_{n+1}); no merge needed ----
        {
            const int sub = lane & 3;
            float pA = 0.f, pB = 0.f;
            if (sub < 2) {
                const float4 eA4 = *(const float4*)sE[j & 1][rg0];
                const float4 eB4 = *(const float4*)sE[j & 1][rg0 + 8];
                const float ea0 = sub ? eA4.z : eA4.x;
                const float ea1 = sub ? eA4.w : eA4.y;
                const float eb0 = sub ? eB4.z : eB4.x;
                const float eb1 = sub ? eB4.w : eB4.y;
                const float sc0 = sub ? s3 : s1;   // w2 : w0
                const float sc1 = sub ? s4 : s2;   // w3 : w1
                const int   w0i = sub << 1;
                if (nT > w0i) {
                    float xA = __expf(ea0 + sc0 - M), xB = __expf(eb0 + sc0 - M);
                    pA += xA * d0;  pB += xB * d2;
                }
                if (nT > w0i + 1) {
                    float xA = __expf(ea1 + sc1 - M), xB = __expf(eb1 + sc1 - M);
                    pA += xA * d1;  pB += xB * d3;
                }
                if (j < WW && (j >> 1) == sub) {   // initial-state (zeros) row
                    float ia = (j & 1) ? ea1 : ea0;
                    float ib = (j & 1) ? eb1 : eb0;
                    pA += 256.0f * __expf(ia - M);
                    pB += 256.0f * __expf(ib - M);
                }
            }
            pA += __shfl_down_sync(0xffffffffu, pA, 1);
            pB += __shfl_down_sync(0xffffffffu, pB, 1);

            float mv = -1e30f;
            if (sub == 0) {
                const float aA = M + __logf(pA);
                const float aB = M + __logf(pB);
                sAlpha[rg0]     = aA;
                sAlpha[rg0 + 8] = aB;
                // v-ring row j (scale σ_j = s0), written once, in-register
                __nv_bfloat16 vA = __float2bfloat16(__expf(aA - s0));
                __nv_bfloat16 vB = __float2bfloat16(__expf(aB - s0));
                *(__nv_bfloat16*)(vsm + slot * ROWB + (rg0 << 1))       = vA;
                *(__nv_bfloat16*)(vsm + slot * ROWB + ((rg0 + 8) << 1)) = vB;
                mv = fmaxf(aA, aB);
            }
            uint32_t km = redux_max_u32(fkey(mv));
            if (lane == 0) sRedL[j & 3][wid] = funkey(km);
        }

        // ---- stage next emissions (loads issued pre-MMA have landed) ----
        if ((j + 1) < JMAX) {
            const float tm = sTm[k_l];
            sE[(j + 1) & 1][k_l][wp]     = (l0 + q0) * tm;
            sE[(j + 1) & 1][k_l][wp + 1] = (l1 + q1) * tm;
        }
        // no trailing sync: bar0 of next step provides all ordering
    }

    // ---- final logsumexp over the last alpha row ----
    __syncthreads();
    {
        float x = (lane < 16) ? sRedL[(JMAX - 1) & 3][lane] : -1e30f;
        const float rowmax = funkey(redux_max_u32(fkey(x)));

        float sv = (tid < KK) ? __expf(sAlpha[tid] - rowmax) : 0.f;
        #pragma unroll
        for (int o = 16; o; o >>= 1) sv += __shfl_xor_sync(0xffffffffu, sv, o);
        if (lane == 0 && wid < 8) sRed[wid] = sv;
        __syncthreads();
        if (tid == 0) {
            float ssum = 0.f;
            #pragma unroll
            for (int i = 0; i < 8; i++) ssum += sRed[i];
            out[b] = rowmax + __logf(ssum);
        }
    }
}

// ---------------------------------------------------------------------------
extern "C" void kernel_launch(void* const* d_in, const int* in_sizes, int n_in,
                              void* d_out, int out_size) {
    const float* logits = (const float*)d_in[0];   // (B,S,W,K) f32
    const float* T      = (const float*)d_in[1];   // (B,K,K)   f32
    const float* hc     = (const float*)d_in[2];   // (B,S,W,K) f32
    const float* tagm   = (const float*)d_in[3];   // (B,K,K)   f32
    const int*   tmask  = (const int*)  d_in[4];   // (B,S)     i32
    float* out = (float*)d_out;                    // (1,B)     f32

    crf_hmma8_kernel<<<BB, NT>>>(logits, T, hc, tagm, tmask, out);
}

// round 16
// speedup vs baseline: 1.0232x; 1.0232x over previous
#include <cuda_runtime.h>
#include <cuda_bf16.h>
#include <cstdint>
#include <math.h>

#define BB 48
#define SS 128
#define WW 4
#define KK 256
#define KH 128
#define NT 512
#define ROWB 528           // v-ring slot stride (bytes): 132 words -> conflict-free
#define TXB 288u           // 64 bf16x2 v-words + 8 warp maxes

typedef unsigned long long ull;

#define MMA_BF16(d0, d1, d2, d3, a, b0, b1)                                   \
    asm volatile(                                                             \
        "mma.sync.aligned.m16n8k16.row.col.f32.bf16.bf16.f32 "                \
        "{%0,%1,%2,%3}, {%4,%5,%6,%7}, {%8,%9}, {%0,%1,%2,%3};"               \
        : "+f"(d0), "+f"(d1), "+f"(d2), "+f"(d3)                              \
        : "r"((a)[0]), "r"((a)[1]), "r"((a)[2]), "r"((a)[3]),                 \
          "r"(b0), "r"(b1))

static __device__ __forceinline__ uint32_t s2u(const void* p) {
    uint32_t a;
    asm("{ .reg .u64 t; cvta.to.shared.u64 t, %1; cvt.u32.u64 %0, t; }"
        : "=r"(a) : "l"(p));
    return a;
}
static __device__ __forceinline__ uint32_t mapa_u(uint32_t a, int rk) {
    uint32_t r;
    asm("mapa.shared::cluster.u32 %0, %1, %2;" : "=r"(r) : "r"(a), "r"(rk));
    return r;
}
static __device__ __forceinline__ void mbar_init(uint32_t mb, uint32_t cnt) {
    asm volatile("mbarrier.init.shared.b64 [%0], %1;" :: "r"(mb), "r"(cnt) : "memory");
}
static __device__ __forceinline__ void mbar_arm(uint32_t mb, uint32_t tx) {
    asm volatile("mbarrier.arrive.expect_tx.shared.b64 _, [%0], %1;"
                 :: "r"(mb), "r"(tx) : "memory");
}
static __device__ __forceinline__ void st_async_b32(uint32_t dst, uint32_t v, uint32_t mb) {
    asm volatile(
        "st.async.weak.shared::cluster.mbarrier::complete_tx::bytes.b32 [%0], %1, [%2];"
        :: "r"(dst), "r"(v), "r"(mb) : "memory");
}
static __device__ __forceinline__ void wait_parity(uint32_t mb, uint32_t par) {
    asm volatile(
        "{\n\t.reg .pred P;\n\t"
        "W_%=:\n\t"
        "mbarrier.try_wait.parity.acquire.cluster.shared::cta.b64 P, [%0], %1, 0x989680;\n\t"
        "@!P bra W_%=;\n\t}"
        :: "r"(mb), "r"(par) : "memory");
}
static __device__ __forceinline__ uint32_t redux_max_u32(uint32_t v) {
    uint32_t r;
    asm("redux.sync.max.u32 %0, %1, 0xffffffff;" : "=r"(r) : "r"(v));
    return r;
}
static __device__ __forceinline__ uint32_t fkey(float f) {
    uint32_t u = __float_as_uint(f);
    return (u & 0x80000000u) ? ~u : (u | 0x80000000u);
}
static __device__ __forceinline__ float funkey(uint32_t k) {
    return __uint_as_float((k & 0x80000000u) ? (k & 0x7fffffffu) : ~k);
}

extern "C" __global__ void __launch_bounds__(NT, 1) __cluster_dims__(2, 1, 1)
crf_hmma9_kernel(const float* __restrict__ logits,
                 const float* __restrict__ T,
                 const float* __restrict__ hc,
                 const float* __restrict__ tagm,
                 const int*   __restrict__ textmask,
                 float* __restrict__ out)
{
    __shared__ float  sAlpha[KH];         // local-half alphas (final lse only)
    __shared__ float  sE[2][KH][4];       // emissions, double-buffered
    __shared__ float4 sPair[2][8][32];    // group B partials, double-buffered
    __shared__ float  sPmax[8][8];        // peer warp maxes per slot
    __shared__ float  sRedL[4][8];        // local warp maxes (4-slot ring)
    __shared__ float  sTm[KH];
    __shared__ float  sRed[32];
    __shared__ float  sFin[2];            // peer {halfmax, halfsum}
    __shared__ ull    sMbar[9];           // 8 step slots + 1 final
    __shared__ __align__(4) unsigned char vsm[8 * ROWB];   // bf16 v-ring, 8 slots

    const int tid  = threadIdx.x;
    const int lane = tid & 31;
    const int wid  = tid >> 5;
    const int b    = blockIdx.x >> 1;
    const int r    = blockIdx.x & 1;
    const int t    = wid & 7;                         // M-tile
    const int khalf = (wid < 8) ? r : (1 - r);        // my kp half

    // ---- length[b] ----
    {
        int tt = (tid < SS) ? textmask[b * SS + tid] : 0;
        #pragma unroll
        for (int o = 16; o; o >>= 1) tt += __shfl_xor_sync(0xffffffffu, tt, o);
        if (lane == 0) sRed[wid] = (float)tt;
    }
    __syncthreads();
    int L = 0;
    #pragma unroll
    for (int i = 0; i < 16; i++) L += (int)sRed[i];
    __syncthreads();
    if (L == 0) { if (r == 0 && tid == 0) out[b] = logf(256.0f); return; }
    const int JMAX = (L < SS) ? L : SS;

    // ---- init barriers + zero v-ring ----
    if (tid < 8) {
        mbar_init(s2u(&sMbar[tid]), 1);
        mbar_arm(s2u(&sMbar[tid]), TXB);
    }
    if (tid == 8) {
        mbar_init(s2u(&sMbar[8]), 1);
        mbar_arm(s2u(&sMbar[8]), 8u);    // final: 2 floats
    }
    {
        uint32_t* vz = (uint32_t*)vsm;
        for (int i = tid; i < (8 * ROWB) / 4; i += NT) vz[i] = 0u;
    }

    // ---- prologue: A frags (my kp half), rows rg0 / rg0+8 ----
    const size_t tb  = (size_t)b * KK * KK;
    const int    lr0 = (t << 4) + (lane >> 2);
    const int    rg0 = r * KH + lr0;
    const int    kq  = (lane & 3) << 1;
    uint32_t A[8][4];
    {
        const float* Tr0 = T    + tb + (size_t)rg0 * KK;
        const float* Mr0 = tagm + tb + (size_t)rg0 * KK;
        const float* Tr1 = Tr0 + 8 * KK;
        const float* Mr1 = Mr0 + 8 * KK;
        #pragma unroll
        for (int c = 0; c < 8; c++) {
            #pragma unroll
            for (int h2 = 0; h2 < 2; h2++) {
                const int kk2 = (khalf * 8 + c) * 16 + kq + h2 * 8;
                float2 t0 = *(const float2*)(Tr0 + kk2);
                float2 m0 = *(const float2*)(Mr0 + kk2);
                float2 t1 = *(const float2*)(Tr1 + kk2);
                float2 m1 = *(const float2*)(Mr1 + kk2);
                __nv_bfloat162 p0 =
                    __floats2bfloat162_rn(__expf(t0.x * m0.x), __expf(t0.y * m0.y));
                __nv_bfloat162 p1 =
                    __floats2bfloat162_rn(__expf(t1.x * m1.x), __expf(t1.y * m1.y));
                A[c][h2 * 2 + 0] = *(uint32_t*)&p0;
                A[c][h2 * 2 + 1] = *(uint32_t*)&p1;
            }
        }
    }

    // ---- sTm + sE[0] ----
    if (tid < KH) sTm[tid] = tagm[tb + r * KH + tid];
    __syncthreads();
    if (tid < 256) {
        const int k_l = tid >> 1, wp = (tid & 1) * 2;
        const size_t ei = (((size_t)b * SS + 0) * WW + wp) * KK + (r * KH + k_l);
        const float tm = sTm[k_l];
        sE[0][k_l][wp]     = (__ldg(logits + ei     ) + __ldg(hc + ei     )) * tm;
        sE[0][k_l][wp + 1] = (__ldg(logits + ei + KK) + __ldg(hc + ei + KK)) * tm;
    }
    __syncthreads();
    asm volatile("barrier.cluster.arrive.aligned;" ::: "memory");
    asm volatile("barrier.cluster.wait.aligned;"   ::: "memory");

    const int      peer     = 1 - r;
    const uint32_t myMbar   = s2u(sMbar);
    const uint32_t peerVsm  = mapa_u(s2u(vsm), peer);
    const uint32_t peerPmax = mapa_u(s2u(sPmax), peer);
    const uint32_t peerFin  = mapa_u(s2u(sFin), peer);
    const uint32_t peerMbar = mapa_u(myMbar, peer);

    // σ history: s0 = σ_j = rowmax_{j-2}; epilogue w=n uses s_{n+1}.
    float s0 = 0.f, s1 = 0.f, s2 = 0.f, s3 = 0.f, s4 = 0.f;

    for (int j = 0; j < JMAX; j++) {
        const int nT   = (j < WW) ? j : WW;
        const int slot = j & 7;

        // ---- σ shift: s0 = rowmax_{j-2} ----
        float ns = 0.f;
        if (j >= 2) {
            float x = -1e30f;
            if (lane < 8)       x = sRedL[(j - 2) & 3][lane];
            else if (lane < 16) x = sPmax[(j - 2) & 7][lane - 8];
            ns = funkey(redux_max_u32(fkey(x)));
        }
        s4 = s3; s3 = s2; s2 = s1; s1 = s0; s0 = ns;
        float M = (j < WW) ? 0.0f : -1e30f;
        if (nT > 0) M = fmaxf(M, s1);
        if (nT > 1) M = fmaxf(M, s2);
        if (nT > 2) M = fmaxf(M, s3);
        if (nT > 3) M = fmaxf(M, s4);

        // ---- group B: wait for peer v-values of slot j-1 (nothing else) ----
        if (wid >= 8 && j > 0) {
            wait_parity(myMbar + (uint32_t)((j - 1) & 7) * 8u,
                        (uint32_t)(((j - 1) >> 3) & 1));
            if (tid == 288)
                mbar_arm(myMbar + (uint32_t)((j - 1) & 7) * 8u, TXB);
        }
        __syncthreads();   // bar0: v-ring slots (j-1..j-4) complete (local+peer)

        // ---- emission LDGs for j+1 (group B) ----
        float l0 = 0.f, l1 = 0.f, q0 = 0.f, q1 = 0.f;
        int k_l = 0, wp = 0;
        if (wid >= 8 && (j + 1) < JMAX) {
            const int idx = tid & 255;
            k_l = idx >> 1; wp = (idx & 1) * 2;
            const size_t ei = (((size_t)b * SS + (j + 1)) * WW + wp) * KK + (r * KH + k_l);
            l0 = __ldg(logits + ei);      q0 = __ldg(hc + ei);
            l1 = __ldg(logits + ei + KK); q1 = __ldg(hc + ei + KK);
        }

        // ---- MMA over my kp half: B rows = ring slots (j-1-n8)&7 ----
        float d0 = 0.f, d1 = 0.f, d2 = 0.f, d3 = 0.f;
        {
            float f0 = 0.f, f1 = 0.f, f2 = 0.f, f3 = 0.f;
            const int      n8    = lane >> 2;
            const uint32_t bboff = (uint32_t)(lane & 3) << 2;
            const uint32_t rowoff =
                (uint32_t)((j - 1 - n8) & 7) * ROWB + (uint32_t)((khalf * 8) << 5) + bboff;
            #pragma unroll
            for (int c = 0; c < 8; c += 2) {
                uint32_t b0 = 0, b1 = 0, b2 = 0, b3 = 0;
                if (n8 < 4) {
                    const unsigned char* vp = vsm + rowoff + (c << 5);
                    b0 = *(const uint32_t*)(vp);
                    b1 = *(const uint32_t*)(vp + 16);
                    b2 = *(const uint32_t*)(vp + 32);
                    b3 = *(const uint32_t*)(vp + 48);
                }
                MMA_BF16(d0, d1, d2, d3, A[c],     b0, b1);
                MMA_BF16(f0, f1, f2, f3, A[c + 1], b2, b3);
            }
            d0 += f0; d1 += f1; d2 += f2; d3 += f3;
        }

        if (wid >= 8) sPair[j & 1][t][lane] = make_float4(d0, d1, d2, d3);
        __syncthreads();   // M1

        if (wid < 8) {
            // ===== merge + split epilogue (w=n uses scale s_{n+1}) =====
            float4 pp = sPair[j & 1][t][lane];
            d0 += pp.x; d1 += pp.y; d2 += pp.z; d3 += pp.w;

            const int sub = lane & 3;
            float pA = 0.f, pB = 0.f;
            if (sub < 2) {
                const float4 eA4 = *(const float4*)sE[j & 1][lr0];
                const float4 eB4 = *(const float4*)sE[j & 1][lr0 + 8];
                const float ea0 = sub ? eA4.z : eA4.x;
                const float ea1 = sub ? eA4.w : eA4.y;
                const float eb0 = sub ? eB4.z : eB4.x;
                const float eb1 = sub ? eB4.w : eB4.y;
                const float sc0 = sub ? s3 : s1;   // w2 : w0
                const float sc1 = sub ? s4 : s2;   // w3 : w1
                const int   w0i = sub << 1;
                if (nT > w0i) {
                    float xA = __expf(ea0 + sc0 - M), xB = __expf(eb0 + sc0 - M);
                    pA += xA * d0;  pB += xB * d2;
                }
                if (nT > w0i + 1) {
                    float xA = __expf(ea1 + sc1 - M), xB = __expf(eb1 + sc1 - M);
                    pA += xA * d1;  pB += xB * d3;
                }
                if (j < WW && (j >> 1) == sub) {   // initial-state (zeros) row
                    float ia = (j & 1) ? ea1 : ea0;
                    float ib = (j & 1) ? eb1 : eb0;
                    pA += 256.0f * __expf(ia - M);
                    pB += 256.0f * __expf(ib - M);
                }
            }
            pA += __shfl_down_sync(0xffffffffu, pA, 1);
            pB += __shfl_down_sync(0xffffffffu, pB, 1);

            float mv = -1e30f;
            uint32_t vAbits = 0, vBbits = 0;
            if (sub == 0) {
                const float aA = M + __logf(pA);
                const float aB = M + __logf(pB);
                sAlpha[lr0]     = aA;
                sAlpha[lr0 + 8] = aB;
                // v-ring row j (scale σ_j = s0)
                __nv_bfloat16 vA = __float2bfloat16(__expf(aA - s0));
                __nv_bfloat16 vB = __float2bfloat16(__expf(aB - s0));
                *(__nv_bfloat16*)(vsm + slot * ROWB + (rg0 << 1))       = vA;
                *(__nv_bfloat16*)(vsm + slot * ROWB + ((rg0 + 8) << 1)) = vB;
                vAbits = (uint32_t)*(unsigned short*)&vA;
                vBbits = (uint32_t)*(unsigned short*)&vB;
                mv = fmaxf(aA, aB);
            }
            // pack neighbor-row pairs: lane 4q gets lane 4(q+1)'s values
            uint32_t nA = __shfl_down_sync(0xffffffffu, vAbits, 4);
            uint32_t nB = __shfl_down_sync(0xffffffffu, vBbits, 4);
            if (sub == 0 && (((lane >> 2) & 1) == 0)) {   // even q: rows rg0, rg0+1
                const uint32_t base = (uint32_t)slot * ROWB + ((uint32_t)rg0 << 1);
                st_async_b32(peerVsm + base,       vAbits | (nA << 16),
                             peerMbar + (uint32_t)slot * 8u);
                st_async_b32(peerVsm + base + 16u, vBbits | (nB << 16),
                             peerMbar + (uint32_t)slot * 8u);
            }
            uint32_t km = redux_max_u32(fkey(mv));
            if (lane == 0) {
                const float wm = funkey(km);
                sRedL[j & 3][t] = wm;
                st_async_b32(peerPmax + ((uint32_t)(slot * 8 + t)) * 4u,
                             __float_as_uint(wm),
                             peerMbar + (uint32_t)slot * 8u);
            }
        } else if ((j + 1) < JMAX) {
            // ===== group B: stage next emissions =====
            const float tm = sTm[k_l];
            sE[(j + 1) & 1][k_l][wp]     = (l0 + q0) * tm;
            sE[(j + 1) & 1][k_l][wp + 1] = (l1 + q1) * tm;
        }
        // no trailing sync: bar0 of next step provides ordering
    }

    // ---- drain last step's flight so the ring mbarrier is settled ----
    if (wid >= 8)
        wait_parity(myMbar + (uint32_t)((JMAX - 1) & 7) * 8u,
                    (uint32_t)(((JMAX - 1) >> 3) & 1));
    __syncthreads();

    // ---- final: local-half lse, exchange 2 scalars, combine ----
    {
        float x = (lane < 8) ? sRedL[(JMAX - 1) & 3][lane] : -1e30f;
        const float hmax = funkey(redux_max_u32(fkey(x)));

        float sv = (tid < KH) ? __expf(sAlpha[tid] - hmax) : 0.f;
        #pragma unroll
        for (int o = 16; o; o >>= 1) sv += __shfl_xor_sync(0xffffffffu, sv, o);
        if (lane == 0 && wid < 4) sRed[wid] = sv;
        __syncthreads();
        if (tid == 0) {
            const float hsum = sRed[0] + sRed[1] + sRed[2] + sRed[3];
            st_async_b32(peerFin,      __float_as_uint(hmax), peerMbar + 64u);
            st_async_b32(peerFin + 4u, __float_as_uint(hsum), peerMbar + 64u);
            wait_parity(myMbar + 64u, 0u);
            if (r == 0) {
                const float pm = sFin[0], ps = sFin[1];
                const float rowmax = fmaxf(hmax, pm);
                const float ssum = hsum * __expf(hmax - rowmax)
                                 + ps   * __expf(pm   - rowmax);
                out[b] = rowmax + __logf(ssum);
            }
        }
    }
    __syncthreads();
    asm volatile("barrier.cluster.arrive.aligned;" ::: "memory");
    asm volatile("barrier.cluster.wait.aligned;"   ::: "memory");
}

// ---------------------------------------------------------------------------
extern "C" void kernel_launch(void* const* d_in, const int* in_sizes, int n_in,
                              void* d_out, int out_size) {
    const float* logits = (const float*)d_in[0];   // (B,S,W,K) f32
    const float* T      = (const float*)d_in[1];   // (B,K,K)   f32
    const float* hc     = (const float*)d_in[2];   // (B,S,W,K) f32
    const float* tagm   = (const float*)d_in[3];   // (B,K,K)   f32
    const int*   tmask  = (const int*)  d_in[4];   // (B,S)     i32
    float* out = (float*)d_out;                    // (1,B)     f32

    crf_hmma9_kernel<<<BB * 2, NT>>>(logits, T, hc, tagm, tmask, out);
}

// round 17
// speedup vs baseline: 1.1852x; 1.1583x over previous
#include <cuda_runtime.h>
#include <cuda_bf16.h>
#include <cstdint>
#include <math.h>

#define BB 48
#define SS 128
#define WW 4
#define KK 256
#define KH 128
#define NT 512
#define ROWB 528           // v-ring slot stride (bytes)
#define TXB 544u           // 128 f32 v + 8 f32 warp maxes

typedef unsigned long long ull;

#define MMA_BF16(d0, d1, d2, d3, a, b0, b1)                                   \
    asm volatile(                                                             \
        "mma.sync.aligned.m16n8k16.row.col.f32.bf16.bf16.f32 "                \
        "{%0,%1,%2,%3}, {%4,%5,%6,%7}, {%8,%9}, {%0,%1,%2,%3};"               \
        : "+f"(d0), "+f"(d1), "+f"(d2), "+f"(d3)                              \
        : "r"((a)[0]), "r"((a)[1]), "r"((a)[2]), "r"((a)[3]),                 \
          "r"(b0), "r"(b1))

static __device__ __forceinline__ uint32_t s2u(const void* p) {
    uint32_t a;
    asm("{ .reg .u64 t; cvta.to.shared.u64 t, %1; cvt.u32.u64 %0, t; }"
        : "=r"(a) : "l"(p));
    return a;
}
static __device__ __forceinline__ uint32_t mapa_u(uint32_t a, int rk) {
    uint32_t r;
    asm("mapa.shared::cluster.u32 %0, %1, %2;" : "=r"(r) : "r"(a), "r"(rk));
    return r;
}
static __device__ __forceinline__ void mbar_init(uint32_t mb, uint32_t cnt) {
    asm volatile("mbarrier.init.shared.b64 [%0], %1;" :: "r"(mb), "r"(cnt) : "memory");
}
static __device__ __forceinline__ void mbar_arm(uint32_t mb, uint32_t tx) {
    asm volatile("mbarrier.arrive.expect_tx.shared.b64 _, [%0], %1;"
                 :: "r"(mb), "r"(tx) : "memory");
}
static __device__ __forceinline__ void st_async_b32(uint32_t dst, uint32_t v, uint32_t mb) {
    asm volatile(
        "st.async.weak.shared::cluster.mbarrier::complete_tx::bytes.b32 [%0], %1, [%2];"
        :: "r"(dst), "r"(v), "r"(mb) : "memory");
}
static __device__ __forceinline__ void wait_parity(uint32_t mb, uint32_t par) {
    asm volatile(
        "{\n\t.reg .pred P;\n\t"
        "W_%=:\n\t"
        "mbarrier.try_wait.parity.acquire.cluster.shared::cta.b64 P, [%0], %1, 0x989680;\n\t"
        "@!P bra W_%=;\n\t}"
        :: "r"(mb), "r"(par) : "memory");
}
static __device__ __forceinline__ uint32_t redux_max_u32(uint32_t v) {
    uint32_t r;
    asm("redux.sync.max.u32 %0, %1, 0xffffffff;" : "=r"(r) : "r"(v));
    return r;
}
static __device__ __forceinline__ uint32_t fkey(float f) {
    uint32_t u = __float_as_uint(f);
    return (u & 0x80000000u) ? ~u : (u | 0x80000000u);
}
static __device__ __forceinline__ float funkey(uint32_t k) {
    return __uint_as_float((k & 0x80000000u) ? (k & 0x7fffffffu) : ~k);
}

extern "C" __global__ void __launch_bounds__(NT, 1) __cluster_dims__(2, 1, 1)
crf_hmma10_kernel(const float* __restrict__ logits,
                  const float* __restrict__ T,
                  const float* __restrict__ hc,
                  const float* __restrict__ tagm,
                  const int*   __restrict__ textmask,
                  float* __restrict__ out)
{
    __shared__ float  sAlpha[KH];         // local-half alphas (final step only)
    __shared__ float  sE[2][KH][4];       // emissions, double-buffered
    __shared__ float4 sPair[2][8][32];    // group B partials
    __shared__ float  sPmax[8][8];        // peer warp maxes per slot
    __shared__ float  sRedL[4][8];        // local warp maxes (4-slot ring)
    __shared__ float  sTm[KH];
    __shared__ float  sRed[32];
    __shared__ float  sFin[2];            // peer {halfmax, halfsum}
    __shared__ float  sVst[2][KH];        // f32 v staging (flight target), 2-deep
    __shared__ ull    sMbar[9];           // 8 step slots + 1 final
    __shared__ __align__(4) unsigned char vsm[8 * ROWB];   // bf16 v-ring

    const int tid  = threadIdx.x;
    const int lane = tid & 31;
    const int wid  = tid >> 5;
    const int b    = blockIdx.x >> 1;
    const int r    = blockIdx.x & 1;
    const int t    = wid & 7;                         // M-tile
    const int khalf = (wid < 8) ? r : (1 - r);        // my kp half

    // ---- length[b] ----
    {
        int tt = (tid < SS) ? textmask[b * SS + tid] : 0;
        #pragma unroll
        for (int o = 16; o; o >>= 1) tt += __shfl_xor_sync(0xffffffffu, tt, o);
        if (lane == 0) sRed[wid] = (float)tt;
    }
    __syncthreads();
    int L = 0;
    #pragma unroll
    for (int i = 0; i < 16; i++) L += (int)sRed[i];
    __syncthreads();
    if (L == 0) { if (r == 0 && tid == 0) out[b] = logf(256.0f); return; }
    const int JMAX = (L < SS) ? L : SS;

    // ---- init barriers + zero v-ring ----
    if (tid < 8) {
        mbar_init(s2u(&sMbar[tid]), 1);
        mbar_arm(s2u(&sMbar[tid]), TXB);
    }
    if (tid == 8) {
        mbar_init(s2u(&sMbar[8]), 1);
        mbar_arm(s2u(&sMbar[8]), 8u);
    }
    {
        uint32_t* vz = (uint32_t*)vsm;
        for (int i = tid; i < (8 * ROWB) / 4; i += NT) vz[i] = 0u;
    }

    // ---- prologue: A frags (my kp half) ----
    const size_t tb  = (size_t)b * KK * KK;
    const int    lr0 = (t << 4) + (lane >> 2);
    const int    rg0 = r * KH + lr0;
    const int    kq  = (lane & 3) << 1;
    uint32_t A[8][4];
    {
        const float* Tr0 = T    + tb + (size_t)rg0 * KK;
        const float* Mr0 = tagm + tb + (size_t)rg0 * KK;
        const float* Tr1 = Tr0 + 8 * KK;
        const float* Mr1 = Mr0 + 8 * KK;
        #pragma unroll
        for (int c = 0; c < 8; c++) {
            #pragma unroll
            for (int h2 = 0; h2 < 2; h2++) {
                const int kk2 = (khalf * 8 + c) * 16 + kq + h2 * 8;
                float2 t0 = *(const float2*)(Tr0 + kk2);
                float2 m0 = *(const float2*)(Mr0 + kk2);
                float2 t1 = *(const float2*)(Tr1 + kk2);
                float2 m1 = *(const float2*)(Mr1 + kk2);
                __nv_bfloat162 p0 =
                    __floats2bfloat162_rn(__expf(t0.x * m0.x), __expf(t0.y * m0.y));
                __nv_bfloat162 p1 =
                    __floats2bfloat162_rn(__expf(t1.x * m1.x), __expf(t1.y * m1.y));
                A[c][h2 * 2 + 0] = *(uint32_t*)&p0;
                A[c][h2 * 2 + 1] = *(uint32_t*)&p1;
            }
        }
    }

    // ---- sTm + sE[0] ----
    if (tid < KH) sTm[tid] = tagm[tb + r * KH + tid];
    __syncthreads();
    if (tid < 256) {
        const int k_l = tid >> 1, wp = (tid & 1) * 2;
        const size_t ei = (((size_t)b * SS + 0) * WW + wp) * KK + (r * KH + k_l);
        const float tm = sTm[k_l];
        sE[0][k_l][wp]     = (__ldg(logits + ei     ) + __ldg(hc + ei     )) * tm;
        sE[0][k_l][wp + 1] = (__ldg(logits + ei + KK) + __ldg(hc + ei + KK)) * tm;
    }
    __syncthreads();
    asm volatile("barrier.cluster.arrive.aligned;" ::: "memory");
    asm volatile("barrier.cluster.wait.aligned;"   ::: "memory");

    const int      peer     = 1 - r;
    const uint32_t myMbar   = s2u(sMbar);
    const uint32_t peerVst  = mapa_u(s2u(sVst), peer);
    const uint32_t peerPmax = mapa_u(s2u(sPmax), peer);
    const uint32_t peerFin  = mapa_u(s2u(sFin), peer);
    const uint32_t peerMbar = mapa_u(myMbar, peer);

    float s0 = 0.f, s1 = 0.f, s2 = 0.f, s3 = 0.f, s4 = 0.f;

    for (int j = 0; j < JMAX; j++) {
        const int nT   = (j < WW) ? j : WW;
        const int slot = j & 7;

        float M = 0.f, cvw = 1.f;
        float wA0 = 0.f, wA1 = 0.f, wB0 = 0.f, wB1 = 0.f, iA = 0.f, iB = 0.f;
        float l0 = 0.f, l1 = 0.f, q0 = 0.f, q1 = 0.f;
        int k_l = 0, wp = 0;

        if (wid < 8) {
            // ===== group A pre-phase: σ, scale, weights (MUFU hidden) =====
            float ns = 0.f;
            if (j >= 2) {
                float x = -1e30f;
                if (lane < 8)       x = sRedL[(j - 2) & 3][lane];
                else if (lane < 16) x = sPmax[(j - 2) & 7][lane - 8];
                ns = funkey(redux_max_u32(fkey(x)));
            }
            s4 = s3; s3 = s2; s2 = s1; s1 = s0; s0 = ns;
            M = (j < WW) ? 0.0f : -1e30f;
            if (nT > 0) M = fmaxf(M, s1);
            if (nT > 1) M = fmaxf(M, s2);
            if (nT > 2) M = fmaxf(M, s3);
            if (nT > 3) M = fmaxf(M, s4);
            cvw = __expf(M - s0);

            const int sub = lane & 3;
            if (sub < 2) {
                const float4 eA4 = *(const float4*)sE[j & 1][lr0];
                const float4 eB4 = *(const float4*)sE[j & 1][lr0 + 8];
                const float ea0 = sub ? eA4.z : eA4.x;
                const float ea1 = sub ? eA4.w : eA4.y;
                const float eb0 = sub ? eB4.z : eB4.x;
                const float eb1 = sub ? eB4.w : eB4.y;
                const float sc0 = sub ? s3 : s1;
                const float sc1 = sub ? s4 : s2;
                const int   w0i = sub << 1;
                if (nT > w0i)     { wA0 = __expf(ea0 + sc0 - M); wB0 = __expf(eb0 + sc0 - M); }
                if (nT > w0i + 1) { wA1 = __expf(ea1 + sc1 - M); wB1 = __expf(eb1 + sc1 - M); }
                if (j < WW && (j >> 1) == sub) {
                    float ia = (j & 1) ? ea1 : ea0;
                    float ib = (j & 1) ? eb1 : eb0;
                    iA = 256.0f * __expf(ia - M);
                    iB = 256.0f * __expf(ib - M);
                }
            }
            asm volatile("bar.sync 1, 256;" ::: "memory");   // A-only: ring local half
        } else {
            // ===== group B pre-phase: LDGs, flight wait, cvt =====
            if ((j + 1) < JMAX) {
                const int idx = tid & 255;
                k_l = idx >> 1; wp = (idx & 1) * 2;
                const size_t ei = (((size_t)b * SS + (j + 1)) * WW + wp) * KK + (r * KH + k_l);
                l0 = __ldg(logits + ei);      q0 = __ldg(hc + ei);
                l1 = __ldg(logits + ei + KK); q1 = __ldg(hc + ei + KK);
            }
            if (j > 0 && tid < 320) {
                wait_parity(myMbar + (uint32_t)((j - 1) & 7) * 8u,
                            (uint32_t)(((j - 1) >> 3) & 1));
                if (tid == 256)
                    mbar_arm(myMbar + (uint32_t)((j - 1) & 7) * 8u, TXB);
                const int idx = tid - 256;   // 0..63
                float f0 = sVst[(j - 1) & 1][2 * idx];
                float f1 = sVst[(j - 1) & 1][2 * idx + 1];
                __nv_bfloat162 vp = __floats2bfloat162_rn(f0, f1);
                *(uint32_t*)(vsm + ((j - 1) & 7) * ROWB
                             + (((1 - r) * KH + 2 * idx) << 1)) = *(uint32_t*)&vp;
            }
            asm volatile("bar.sync 2, 256;" ::: "memory");   // B-only: peer half ready
        }

        // ---- common MMA over my kp half ----
        float d0 = 0.f, d1 = 0.f, d2 = 0.f, d3 = 0.f;
        {
            float f0 = 0.f, f1 = 0.f, f2 = 0.f, f3 = 0.f;
            const int      n8    = lane >> 2;
            const uint32_t bboff = (uint32_t)(lane & 3) << 2;
            const uint32_t rowoff =
                (uint32_t)((j - 1 - n8) & 7) * ROWB + (uint32_t)((khalf * 8) << 5) + bboff;
            #pragma unroll
            for (int c = 0; c < 8; c += 2) {
                uint32_t b0 = 0, b1 = 0, b2 = 0, b3 = 0;
                if (n8 < 4) {
                    const unsigned char* vp = vsm + rowoff + (c << 5);
                    b0 = *(const uint32_t*)(vp);
                    b1 = *(const uint32_t*)(vp + 16);
                    b2 = *(const uint32_t*)(vp + 32);
                    b3 = *(const uint32_t*)(vp + 48);
                }
                MMA_BF16(d0, d1, d2, d3, A[c],     b0, b1);
                MMA_BF16(f0, f1, f2, f3, A[c + 1], b2, b3);
            }
            d0 += f0; d1 += f1; d2 += f2; d3 += f3;
        }

        if (wid >= 8) {
            sPair[j & 1][t][lane] = make_float4(d0, d1, d2, d3);
            if ((j + 1) < JMAX) {        // stage next emissions pre-M1
                const float tm = sTm[k_l];
                sE[(j + 1) & 1][k_l][wp]     = (l0 + q0) * tm;
                sE[(j + 1) & 1][k_l][wp + 1] = (l1 + q1) * tm;
            }
        }
        __syncthreads();   // M1

        if (wid < 8) {
            // ===== epilogue: zero MUFU on critical path =====
            float4 pp = sPair[j & 1][t][lane];
            d0 += pp.x; d1 += pp.y; d2 += pp.z; d3 += pp.w;

            float pA = wA0 * d0 + wA1 * d1 + iA;
            float pB = wB0 * d2 + wB1 * d3 + iB;
            pA += __shfl_down_sync(0xffffffffu, pA, 1);
            pB += __shfl_down_sync(0xffffffffu, pB, 1);

            float mv = -1e30f;
            if ((lane & 3) == 0) {
                const float vA = pA * cvw;        // v = tot * exp(M - σ_j)
                const float vB = pB * cvw;
                st_async_b32(peerVst + (uint32_t)(j & 1) * 512u + (uint32_t)lr0 * 4u,
                             __float_as_uint(vA), peerMbar + (uint32_t)slot * 8u);
                st_async_b32(peerVst + (uint32_t)(j & 1) * 512u + (uint32_t)(lr0 + 8) * 4u,
                             __float_as_uint(vB), peerMbar + (uint32_t)slot * 8u);
                __nv_bfloat16 hA = __float2bfloat16(vA);
                __nv_bfloat16 hB = __float2bfloat16(vB);
                *(__nv_bfloat16*)(vsm + slot * ROWB + (rg0 << 1))       = hA;
                *(__nv_bfloat16*)(vsm + slot * ROWB + ((rg0 + 8) << 1)) = hB;
                mv = fmaxf(pA, pB);
                if (j + 1 == JMAX) {
                    sAlpha[lr0]     = M + __logf(pA);
                    sAlpha[lr0 + 8] = M + __logf(pB);
                }
            }
            uint32_t km = redux_max_u32(fkey(mv));
            if (lane == 0) {
                const float wm = M + __logf(funkey(km));   // off critical path
                sRedL[j & 3][t] = wm;
                st_async_b32(peerPmax + ((uint32_t)(slot * 8 + t)) * 4u,
                             __float_as_uint(wm),
                             peerMbar + (uint32_t)slot * 8u);
            }
        }
        // no trailing sync
    }

    // ---- drain last flight ----
    if (wid >= 8)
        wait_parity(myMbar + (uint32_t)((JMAX - 1) & 7) * 8u,
                    (uint32_t)(((JMAX - 1) >> 3) & 1));
    __syncthreads();

    // ---- final: local-half lse + 2-scalar exchange ----
    {
        float x = (lane < 8) ? sRedL[(JMAX - 1) & 3][lane] : -1e30f;
        const float hmax = funkey(redux_max_u32(fkey(x)));

        float sv = (tid < KH) ? __expf(sAlpha[tid] - hmax) : 0.f;
        #pragma unroll
        for (int o = 16; o; o >>= 1) sv += __shfl_xor_sync(0xffffffffu, sv, o);
        if (lane == 0 && wid < 4) sRed[wid] = sv;
        __syncthreads();
        if (tid == 0) {
            const float hsum = sRed[0] + sRed[1] + sRed[2] + sRed[3];
            st_async_b32(peerFin,      __float_as_uint(hmax), peerMbar + 64u);
            st_async_b32(peerFin + 4u, __float_as_uint(hsum), peerMbar + 64u);
            wait_parity(myMbar + 64u, 0u);
            if (r == 0) {
                const float pm = sFin[0], ps = sFin[1];
                const float rowmax = fmaxf(hmax, pm);
                const float ssum = hsum * __expf(hmax - rowmax)
                                 + ps   * __expf(pm   - rowmax);
                out[b] = rowmax + __logf(ssum);
            }
        }
    }
    __syncthreads();
    asm volatile("barrier.cluster.arrive.aligned;" ::: "memory");
    asm volatile("barrier.cluster.wait.aligned;"   ::: "memory");
}

// ---------------------------------------------------------------------------
extern "C" void kernel_launch(void* const* d_in, const int* in_sizes, int n_in,
                              void* d_out, int out_size) {
    const float* logits = (const float*)d_in[0];   // (B,S,W,K) f32
    const float* T      = (const float*)d_in[1];   // (B,K,K)   f32
    const float* hc     = (const float*)d_in[2];   // (B,S,W,K) f32
    const float* tagm   = (const float*)d_in[3];   // (B,K,K)   f32
    const int*   tmask  = (const int*)  d_in[4];   // (B,S)     i32
    float* out = (float*)d_out;                    // (1,B)     f32

    crf_hmma10_kernel<<<BB * 2, NT>>>(logits, T, hc, tagm, tmask, out);
}